// round 1
// baseline (speedup 1.0000x reference)
#include <cuda_runtime.h>
#include <math.h>
#include <stdint.h>

// Causal attention, B=2 H=16 S=2048 D=128, fp32.
// FlashAttention-2 style, fp32 FFMA pipe, CTA = one (b,h) x 64-query tile.

#define BM 64
#define BN 64
#define DH 128
#define NT 256

// smem (floats): Qt[128][64] | Kt[128][64] | Vs[2][64][128] | Ps[64][68]
#define QT_OFF   0
#define KT_OFF   (128*64)
#define VS_OFF   (2*128*64)
#define PS_OFF   (VS_OFF + 2*64*128)
#define SMEM_FLOATS (PS_OFF + 64*68)
#define SMEM_BYTES  (SMEM_FLOATS * 4)

__device__ __forceinline__ void cp_async16(void* smem_dst, const void* gmem_src) {
    unsigned sa = (unsigned)__cvta_generic_to_shared(smem_dst);
    asm volatile("cp.async.cg.shared.global [%0], [%1], 16;\n" :: "r"(sa), "l"(gmem_src) : "memory");
}

__global__ __launch_bounds__(NT, 1)
void fa_fp32_kernel(const float* __restrict__ Qg, const float* __restrict__ Kg,
                    const float* __restrict__ Vg, float* __restrict__ Og)
{
    extern __shared__ float sm[];
    float* Qt = sm + QT_OFF;   // [d][row], stride 64
    float* Kt = sm + KT_OFF;   // [d][col], stride 64
    float* Vs = sm + VS_OFF;   // 2 x [k][d], stride 128
    float* Ps = sm + PS_OFF;   // [row][k],  stride 68

    const int tid = threadIdx.x;
    const int tr = tid >> 4;        // 0..15 (row group)
    const int tc = tid & 15;        // 0..15 (col / d group)
    const int qt  = (int)(gridDim.x - 1) - (int)blockIdx.x;   // heavy tiles first
    const size_t base = (size_t)blockIdx.y * (size_t)(2048 * 128);
    const int q0 = qt * BM;

    // ---------------- fill Qt (transposed, scale folded: log2(e)/sqrt(D)) -------------
    {
        const float qs = 1.4426950408889634f * 0.08838834764831845f;
        const int row  = tid & 63;
        const int dblk = (tid >> 6) << 5;     // 0,32,64,96
        const float4* g = reinterpret_cast<const float4*>(Qg + base + (size_t)(q0 + row) * DH + dblk);
        #pragma unroll
        for (int i = 0; i < 8; i++) {
            float4 t = g[i];
            int d = dblk + 4 * i;
            Qt[(d + 0) * 64 + row] = t.x * qs;
            Qt[(d + 1) * 64 + row] = t.y * qs;
            Qt[(d + 2) * 64 + row] = t.z * qs;
            Qt[(d + 3) * 64 + row] = t.w * qs;
        }
    }

    // accumulators
    float o[4][8];
    float m[4], l[4];
    #pragma unroll
    for (int a = 0; a < 4; a++) {
        m[a] = -1e30f; l[a] = 0.f;
        #pragma unroll
        for (int c = 0; c < 8; c++) o[a][c] = 0.f;
    }

    // prefetch K tile 0 into registers (conflict-free transpose mapping)
    const int krow  = tid & 63;
    const int kdblk = (tid >> 6) << 5;
    float4 kreg[8];
    {
        const float4* g = reinterpret_cast<const float4*>(Kg + base + (size_t)krow * DH + kdblk);
        #pragma unroll
        for (int i = 0; i < 8; i++) kreg[i] = g[i];
    }
    // cp.async V tile 0 into buffer 0
    {
        const float* src = Vg + base;
        #pragma unroll
        for (int i = 0; i < 8; i++) {
            int f = i * 256 + tid;
            cp_async16(Vs + 4 * f, src + 4 * f);
        }
        asm volatile("cp.async.commit_group;\n" ::: "memory");
    }

    for (int j = 0; j <= qt; j++) {
        __syncthreads();   // prev iter's Kt/Ps/V reads all done

        // store K tile j (registers -> transposed smem). Lanes of a warp hit 32
        // distinct rows -> 32 distinct banks, conflict-free scalar STS.
        #pragma unroll
        for (int i = 0; i < 8; i++) {
            int d = kdblk + 4 * i;
            Kt[(d + 0) * 64 + krow] = kreg[i].x;
            Kt[(d + 1) * 64 + krow] = kreg[i].y;
            Kt[(d + 2) * 64 + krow] = kreg[i].z;
            Kt[(d + 3) * 64 + krow] = kreg[i].w;
        }

        if (j < qt) {
            // prefetch K_{j+1} into regs, V_{j+1} into alternate smem buffer
            const float4* g = reinterpret_cast<const float4*>(
                Kg + base + (size_t)((j + 1) * BN + krow) * DH + kdblk);
            #pragma unroll
            for (int i = 0; i < 8; i++) kreg[i] = g[i];

            const float* src = Vg + base + (size_t)(j + 1) * (BN * DH);
            float* dst = Vs + ((j + 1) & 1) * (BN * DH);
            #pragma unroll
            for (int i = 0; i < 8; i++) {
                int f = i * 256 + tid;
                cp_async16(dst + 4 * f, src + 4 * f);
            }
            asm volatile("cp.async.commit_group;\n" ::: "memory");
            asm volatile("cp.async.wait_group 1;\n" ::: "memory");
        } else {
            asm volatile("cp.async.wait_group 0;\n" ::: "memory");
        }
        __syncthreads();   // Kt + V_j visible

        // ---------------- S = Q K^T (already in log2 domain) ----------------
        float s[4][4];
        #pragma unroll
        for (int a = 0; a < 4; a++)
            #pragma unroll
            for (int b = 0; b < 4; b++) s[a][b] = 0.f;

        #pragma unroll 8
        for (int d = 0; d < DH; d++) {
            float4 qf = *reinterpret_cast<const float4*>(Qt + d * 64 + 4 * tr); // broadcast
            float4 kf = *reinterpret_cast<const float4*>(Kt + d * 64 + 4 * tc); // conflict-free
            float qa[4] = {qf.x, qf.y, qf.z, qf.w};
            float ka[4] = {kf.x, kf.y, kf.z, kf.w};
            #pragma unroll
            for (int a = 0; a < 4; a++)
                #pragma unroll
                for (int b = 0; b < 4; b++)
                    s[a][b] = fmaf(qa[a], ka[b], s[a][b]);
        }

        // causal mask on the diagonal tile
        if (j == qt) {
            #pragma unroll
            for (int a = 0; a < 4; a++)
                #pragma unroll
                for (int b = 0; b < 4; b++)
                    if (4 * tc + b > 4 * tr + a) s[a][b] = -1e30f;
        }

        // ---------------- online softmax (exp2 domain) ----------------
        #pragma unroll
        for (int a = 0; a < 4; a++) {
            float rm = fmaxf(fmaxf(s[a][0], s[a][1]), fmaxf(s[a][2], s[a][3]));
            #pragma unroll
            for (int off = 8; off > 0; off >>= 1)
                rm = fmaxf(rm, __shfl_xor_sync(0xffffffffu, rm, off, 16));
            float mn = fmaxf(m[a], rm);
            float sf = exp2f(m[a] - mn);
            m[a] = mn;
            float rs = 0.f;
            #pragma unroll
            for (int b = 0; b < 4; b++) { s[a][b] = exp2f(s[a][b] - mn); rs += s[a][b]; }
            #pragma unroll
            for (int off = 8; off > 0; off >>= 1)
                rs += __shfl_xor_sync(0xffffffffu, rs, off, 16);
            l[a] = l[a] * sf + rs;
            #pragma unroll
            for (int c = 0; c < 8; c++) o[a][c] *= sf;
            // P[row][k], stride 68 -> STS.128 conflict-free
            *reinterpret_cast<float4*>(Ps + (4 * tr + a) * 68 + 4 * tc) =
                make_float4(s[a][0], s[a][1], s[a][2], s[a][3]);
        }
        __syncthreads();   // P visible

        // ---------------- O += P @ V ----------------
        const float* vb = Vs + (j & 1) * (BN * DH);
        #pragma unroll 2
        for (int k4 = 0; k4 < 16; k4++) {
            float pr[4][4];
            #pragma unroll
            for (int a = 0; a < 4; a++) {
                float4 t = *reinterpret_cast<const float4*>(Ps + (4 * tr + a) * 68 + 4 * k4);
                pr[a][0] = t.x; pr[a][1] = t.y; pr[a][2] = t.z; pr[a][3] = t.w;
            }
            #pragma unroll
            for (int kk = 0; kk < 4; kk++) {
                const float* vrow = vb + (4 * k4 + kk) * DH + 8 * tc;
                float4 v0 = *reinterpret_cast<const float4*>(vrow);
                float4 v1 = *reinterpret_cast<const float4*>(vrow + 4);
                float va[8] = {v0.x, v0.y, v0.z, v0.w, v1.x, v1.y, v1.z, v1.w};
                #pragma unroll
                for (int a = 0; a < 4; a++)
                    #pragma unroll
                    for (int c = 0; c < 8; c++)
                        o[a][c] = fmaf(pr[a][kk], va[c], o[a][c]);
            }
        }
    }

    // ---------------- epilogue ----------------
    #pragma unroll
    for (int a = 0; a < 4; a++) {
        float inv = 1.0f / l[a];
        float* dst = Og + base + (size_t)(q0 + 4 * tr + a) * DH + 8 * tc;
        float4 w0 = make_float4(o[a][0] * inv, o[a][1] * inv, o[a][2] * inv, o[a][3] * inv);
        float4 w1 = make_float4(o[a][4] * inv, o[a][5] * inv, o[a][6] * inv, o[a][7] * inv);
        *reinterpret_cast<float4*>(dst)     = w0;
        *reinterpret_cast<float4*>(dst + 4) = w1;
    }
}

extern "C" void kernel_launch(void* const* d_in, const int* in_sizes, int n_in,
                              void* d_out, int out_size)
{
    const float* q = (const float*)d_in[0];
    const float* k = (const float*)d_in[1];
    const float* v = (const float*)d_in[2];
    float* o = (float*)d_out;

    // B*H derived from input size; S=2048, D=128 fixed for this problem.
    int bh = in_sizes[0] / (2048 * 128);      // = 32
    int nqt = 2048 / BM;                      // = 32

    cudaFuncSetAttribute(fa_fp32_kernel,
                         cudaFuncAttributeMaxDynamicSharedMemorySize, SMEM_BYTES);

    dim3 grid(nqt, bh);
    fa_fp32_kernel<<<grid, NT, SMEM_BYTES>>>(q, k, v, o);
}

// round 2
// speedup vs baseline: 1.0005x; 1.0005x over previous
#include <cuda_runtime.h>
#include <math.h>
#include <stdint.h>

// Causal attention, B=2 H=16 S=2048 D=128, fp32.
// FlashAttention-2 style, fp32 FFMA pipe, CTA = one (b,h) x 64-query tile.

#define BM 64
#define BN 64
#define DH 128
#define NT 256

// smem (floats): Qt[128][64] | Kt[128][64] | Vs[2][64][128] | Ps[64][68]
#define QT_OFF   0
#define KT_OFF   (128*64)
#define VS_OFF   (2*128*64)
#define PS_OFF   (VS_OFF + 2*64*128)
#define SMEM_FLOATS (PS_OFF + 64*68)
#define SMEM_BYTES  (SMEM_FLOATS * 4)

__device__ __forceinline__ void cp_async16(void* smem_dst, const void* gmem_src) {
    unsigned sa = (unsigned)__cvta_generic_to_shared(smem_dst);
    asm volatile("cp.async.cg.shared.global [%0], [%1], 16;\n" :: "r"(sa), "l"(gmem_src) : "memory");
}

__global__ __launch_bounds__(NT, 1)
void fa_fp32_kernel(const float* __restrict__ Qg, const float* __restrict__ Kg,
                    const float* __restrict__ Vg, float* __restrict__ Og)
{
    extern __shared__ float sm[];
    float* Qt = sm + QT_OFF;   // [d][row], stride 64
    float* Kt = sm + KT_OFF;   // [d][col], stride 64
    float* Vs = sm + VS_OFF;   // 2 x [k][d], stride 128
    float* Ps = sm + PS_OFF;   // [row][k],  stride 68

    const int tid = threadIdx.x;
    const int tr = tid >> 4;        // 0..15 (row group)
    const int tc = tid & 15;        // 0..15 (col / d group)
    const int qt  = (int)(gridDim.x - 1) - (int)blockIdx.x;   // heavy tiles first
    const size_t base = (size_t)blockIdx.y * (size_t)(2048 * 128);
    const int q0 = qt * BM;

    // ---------------- fill Qt (transposed, scale folded: log2(e)/sqrt(D)) -------------
    {
        const float qs = 1.4426950408889634f * 0.08838834764831845f;
        const int row  = tid & 63;
        const int dblk = (tid >> 6) << 5;     // 0,32,64,96
        const float4* g = reinterpret_cast<const float4*>(Qg + base + (size_t)(q0 + row) * DH + dblk);
        #pragma unroll
        for (int i = 0; i < 8; i++) {
            float4 t = g[i];
            int d = dblk + 4 * i;
            Qt[(d + 0) * 64 + row] = t.x * qs;
            Qt[(d + 1) * 64 + row] = t.y * qs;
            Qt[(d + 2) * 64 + row] = t.z * qs;
            Qt[(d + 3) * 64 + row] = t.w * qs;
        }
    }

    // accumulators
    float o[4][8];
    float m[4], l[4];
    #pragma unroll
    for (int a = 0; a < 4; a++) {
        m[a] = -1e30f; l[a] = 0.f;
        #pragma unroll
        for (int c = 0; c < 8; c++) o[a][c] = 0.f;
    }

    // prefetch K tile 0 into registers (conflict-free transpose mapping)
    const int krow  = tid & 63;
    const int kdblk = (tid >> 6) << 5;
    float4 kreg[8];
    {
        const float4* g = reinterpret_cast<const float4*>(Kg + base + (size_t)krow * DH + kdblk);
        #pragma unroll
        for (int i = 0; i < 8; i++) kreg[i] = g[i];
    }
    // cp.async V tile 0 into buffer 0
    {
        const float* src = Vg + base;
        #pragma unroll
        for (int i = 0; i < 8; i++) {
            int f = i * 256 + tid;
            cp_async16(Vs + 4 * f, src + 4 * f);
        }
        asm volatile("cp.async.commit_group;\n" ::: "memory");
    }

    for (int j = 0; j <= qt; j++) {
        __syncthreads();   // prev iter's Kt/Ps/V reads all done

        // store K tile j (registers -> transposed smem). Lanes of a warp hit 32
        // distinct rows -> 32 distinct banks, conflict-free scalar STS.
        #pragma unroll
        for (int i = 0; i < 8; i++) {
            int d = kdblk + 4 * i;
            Kt[(d + 0) * 64 + krow] = kreg[i].x;
            Kt[(d + 1) * 64 + krow] = kreg[i].y;
            Kt[(d + 2) * 64 + krow] = kreg[i].z;
            Kt[(d + 3) * 64 + krow] = kreg[i].w;
        }

        if (j < qt) {
            // prefetch K_{j+1} into regs, V_{j+1} into alternate smem buffer
            const float4* g = reinterpret_cast<const float4*>(
                Kg + base + (size_t)((j + 1) * BN + krow) * DH + kdblk);
            #pragma unroll
            for (int i = 0; i < 8; i++) kreg[i] = g[i];

            const float* src = Vg + base + (size_t)(j + 1) * (BN * DH);
            float* dst = Vs + ((j + 1) & 1) * (BN * DH);
            #pragma unroll
            for (int i = 0; i < 8; i++) {
                int f = i * 256 + tid;
                cp_async16(dst + 4 * f, src + 4 * f);
            }
            asm volatile("cp.async.commit_group;\n" ::: "memory");
            asm volatile("cp.async.wait_group 1;\n" ::: "memory");
        } else {
            asm volatile("cp.async.wait_group 0;\n" ::: "memory");
        }
        __syncthreads();   // Kt + V_j visible

        // ---------------- S = Q K^T (already in log2 domain) ----------------
        float s[4][4];
        #pragma unroll
        for (int a = 0; a < 4; a++)
            #pragma unroll
            for (int b = 0; b < 4; b++) s[a][b] = 0.f;

        #pragma unroll 8
        for (int d = 0; d < DH; d++) {
            float4 qf = *reinterpret_cast<const float4*>(Qt + d * 64 + 4 * tr); // broadcast
            float4 kf = *reinterpret_cast<const float4*>(Kt + d * 64 + 4 * tc); // conflict-free
            float qa[4] = {qf.x, qf.y, qf.z, qf.w};
            float ka[4] = {kf.x, kf.y, kf.z, kf.w};
            #pragma unroll
            for (int a = 0; a < 4; a++)
                #pragma unroll
                for (int b = 0; b < 4; b++)
                    s[a][b] = fmaf(qa[a], ka[b], s[a][b]);
        }

        // causal mask on the diagonal tile
        if (j == qt) {
            #pragma unroll
            for (int a = 0; a < 4; a++)
                #pragma unroll
                for (int b = 0; b < 4; b++)
                    if (4 * tc + b > 4 * tr + a) s[a][b] = -1e30f;
        }

        // ---------------- online softmax (exp2 domain) ----------------
        #pragma unroll
        for (int a = 0; a < 4; a++) {
            float rm = fmaxf(fmaxf(s[a][0], s[a][1]), fmaxf(s[a][2], s[a][3]));
            #pragma unroll
            for (int off = 8; off > 0; off >>= 1)
                rm = fmaxf(rm, __shfl_xor_sync(0xffffffffu, rm, off, 16));
            float mn = fmaxf(m[a], rm);
            float sf = exp2f(m[a] - mn);
            m[a] = mn;
            float rs = 0.f;
            #pragma unroll
            for (int b = 0; b < 4; b++) { s[a][b] = exp2f(s[a][b] - mn); rs += s[a][b]; }
            #pragma unroll
            for (int off = 8; off > 0; off >>= 1)
                rs += __shfl_xor_sync(0xffffffffu, rs, off, 16);
            l[a] = l[a] * sf + rs;
            #pragma unroll
            for (int c = 0; c < 8; c++) o[a][c] *= sf;
            // P[row][k], stride 68 -> STS.128 conflict-free
            *reinterpret_cast<float4*>(Ps + (4 * tr + a) * 68 + 4 * tc) =
                make_float4(s[a][0], s[a][1], s[a][2], s[a][3]);
        }
        __syncthreads();   // P visible

        // ---------------- O += P @ V ----------------
        const float* vb = Vs + (j & 1) * (BN * DH);
        #pragma unroll 2
        for (int k4 = 0; k4 < 16; k4++) {
            float pr[4][4];
            #pragma unroll
            for (int a = 0; a < 4; a++) {
                float4 t = *reinterpret_cast<const float4*>(Ps + (4 * tr + a) * 68 + 4 * k4);
                pr[a][0] = t.x; pr[a][1] = t.y; pr[a][2] = t.z; pr[a][3] = t.w;
            }
            #pragma unroll
            for (int kk = 0; kk < 4; kk++) {
                const float* vrow = vb + (4 * k4 + kk) * DH + 8 * tc;
                float4 v0 = *reinterpret_cast<const float4*>(vrow);
                float4 v1 = *reinterpret_cast<const float4*>(vrow + 4);
                float va[8] = {v0.x, v0.y, v0.z, v0.w, v1.x, v1.y, v1.z, v1.w};
                #pragma unroll
                for (int a = 0; a < 4; a++)
                    #pragma unroll
                    for (int c = 0; c < 8; c++)
                        o[a][c] = fmaf(pr[a][kk], va[c], o[a][c]);
            }
        }
    }

    // ---------------- epilogue ----------------
    #pragma unroll
    for (int a = 0; a < 4; a++) {
        float inv = 1.0f / l[a];
        float* dst = Og + base + (size_t)(q0 + 4 * tr + a) * DH + 8 * tc;
        float4 w0 = make_float4(o[a][0] * inv, o[a][1] * inv, o[a][2] * inv, o[a][3] * inv);
        float4 w1 = make_float4(o[a][4] * inv, o[a][5] * inv, o[a][6] * inv, o[a][7] * inv);
        *reinterpret_cast<float4*>(dst)     = w0;
        *reinterpret_cast<float4*>(dst + 4) = w1;
    }
}

extern "C" void kernel_launch(void* const* d_in, const int* in_sizes, int n_in,
                              void* d_out, int out_size)
{
    const float* q = (const float*)d_in[0];
    const float* k = (const float*)d_in[1];
    const float* v = (const float*)d_in[2];
    float* o = (float*)d_out;

    // B*H derived from input size; S=2048, D=128 fixed for this problem.
    int bh = in_sizes[0] / (2048 * 128);      // = 32
    int nqt = 2048 / BM;                      // = 32

    cudaFuncSetAttribute(fa_fp32_kernel,
                         cudaFuncAttributeMaxDynamicSharedMemorySize, SMEM_BYTES);

    dim3 grid(nqt, bh);
    fa_fp32_kernel<<<grid, NT, SMEM_BYTES>>>(q, k, v, o);
}